// round 10
// baseline (speedup 1.0000x reference)
#include <cuda_runtime.h>

#define B_      32
#define T_      512
#define D_      384
#define MAXOUT  3584                    // T_ * (8 - 1)
#define VEC     (D_ / 4)                // 96 float4 per row
#define THREADS 256
#define UNROLL  8
#define TILES   8                       // tiles per block (amortize scan/search)
#define F4_PER_TILE  (THREADS * UNROLL) // 2048
#define F4_PER_BLOCK (F4_PER_TILE * TILES) // 16384
#define F4_PER_BATCH (MAXOUT * VEC)     // 344064
#define BLOCKS_PER_BATCH (F4_PER_BATCH / F4_PER_BLOCK) // 21, exact
#define NROWS   176                     // distinct output rows per block (<=172) + pad

__global__ void __launch_bounds__(THREADS) lr_fused_kernel(
    const int*    __restrict__ dur,
    const float4* __restrict__ in,
    float4*       __restrict__ out)
{
    __shared__ int cum[T_];
    __shared__ int wsum[8];
    __shared__ int s_idx[NROWS];        // source frame per local row (-1 = zero)

    const int tid = threadIdx.x;
    const int b   = blockIdx.y;

    // ── One inclusive scan of this batch's 512 durations per block ──
    const int2 dp = ((const int2*)(dur + b * T_))[tid];
    const int  d0 = max(dp.x, 0);
    const int  d1 = max(dp.y, 0);

    const int lane = tid & 31;
    const int warp = tid >> 5;

    int v = d0 + d1;
    #pragma unroll
    for (int o = 1; o < 32; o <<= 1) {
        int n = __shfl_up_sync(0xffffffffu, v, o);
        if (lane >= o) v += n;
    }
    if (lane == 31) wsum[warp] = v;
    __syncthreads();
    if (warp == 0) {
        int w = (lane < 8) ? wsum[lane] : 0;
        #pragma unroll
        for (int o = 1; o < 8; o <<= 1) {
            int n = __shfl_up_sync(0xffffffffu, w, o);
            if (lane >= o) w += n;
        }
        if (lane < 8) wsum[lane] = w;
    }
    __syncthreads();

    const int incl = v + (warp > 0 ? wsum[warp - 1] : 0);
    cum[2 * tid + 1] = incl;
    cum[2 * tid]     = incl - d1;
    __syncthreads();

    const int total    = cum[T_ - 1];
    const int f4_base  = blockIdx.x * F4_PER_BLOCK;
    const int row_base = f4_base / VEC;

    // ── Row->frame table for ALL 8 tiles, built once ──
    if (tid < NROWS) {
        const int row = row_base + tid;
        int idx = -1;
        if (row < total) {
            int p = 0;
            #pragma unroll
            for (int step = 256; step > 0; step >>= 1)
                if (cum[p + step - 1] <= row) p += step;
            idx = min(p, T_ - 1);
        }
        s_idx[tid] = idx;
    }
    __syncthreads();

    const float4* __restrict__ inb  = in  + b * (T_ * VEC);
    float4*       __restrict__ outb = out + b * F4_PER_BATCH;
    const float4 z = make_float4(0.f, 0.f, 0.f, 0.f);

    // ── 8 tiles back-to-back, no further syncs: continuous store stream ──
    #pragma unroll 1
    for (int t = 0; t < TILES; ++t) {
        const int tile_f4 = f4_base + t * F4_PER_TILE;
        const int posb    = tile_f4 + tid;

        if (tile_f4 / VEC >= total) {
            // Tile entirely past valid region: pure zero fill.
            #pragma unroll
            for (int j = 0; j < UNROLL; ++j)
                __stcs(&outb[posb + j * THREADS], z);
            continue;
        }

        int idx[UNROLL], col[UNROLL];
        #pragma unroll
        for (int j = 0; j < UNROLL; ++j) {
            const int pos = posb + j * THREADS;
            const int row = pos / VEC;
            col[j] = pos - row * VEC;
            idx[j] = s_idx[row - row_base];
        }

        float4 val[UNROLL];
        #pragma unroll
        for (int j = 0; j < UNROLL; ++j) {
            const int ic = max(idx[j], 0);
            val[j] = __ldg(&inb[ic * VEC + col[j]]);
            if (idx[j] < 0) val[j] = z;
        }

        #pragma unroll
        for (int j = 0; j < UNROLL; ++j)
            __stcs(&outb[posb + j * THREADS], val[j]);
    }
}

extern "C" void kernel_launch(void* const* d_in, const int* in_sizes, int n_in,
                              void* d_out, int out_size)
{
    const float* x   = (const float*)d_in[0];   // [B, T, D] float32
    const int*   dur = (const int*)d_in[1];     // [B, T] int32
    float* out = (float*)d_out;                 // [B, MAXOUT, D] float32

    dim3 grid(BLOCKS_PER_BATCH, B_);
    lr_fused_kernel<<<grid, THREADS>>>(dur, (const float4*)x, (float4*)out);
}